// round 10
// baseline (speedup 1.0000x reference)
#include <cuda_runtime.h>
#include <cuda_bf16.h>
#include <math.h>
#include <stdint.h>

#define B_ 2
#define DEPTH_ 4
#define HEADS_ 8
#define DIM_ 1024
#define DH_ 128
#define SEQ_ 1024
#define MEM_ 1024
#define LMEM_ 256
#define VOCAB_ 32000
#define KVLEN_ (LMEM_ + MEM_ + SEQ_)   // 2304
typedef __nv_bfloat16 bf;

// ---------------- fp32 scratch ----------------
__device__ float g_h[B_ * SEQ_ * DIM_];
__device__ float g_kv[B_ * KVLEN_ * 2 * DIM_];
__device__ float g_qk[(size_t)B_ * HEADS_ * SEQ_ * KVLEN_];
__device__ float g_qp[(size_t)B_ * HEADS_ * SEQ_ * KVLEN_];
__device__ float g_kvm[(size_t)DEPTH_ * B_ * KVLEN_ * 2 * DIM_];
__device__ float g_qm[DEPTH_ * B_ * LMEM_ * DIM_];
__device__ float g_ctx[DEPTH_ * B_ * HEADS_ * DH_ * DH_];

// ---------------- packed bf16 hi/lo scratch (per 32 logical cols: 32 hi | 32 lo) ----------------
__device__ bf s_wqT[DEPTH_ * DIM_ * 2 * DIM_];
__device__ bf s_wkvT[(size_t)DEPTH_ * 2 * DIM_ * 2 * DIM_];
__device__ bf s_woT[DEPTH_ * DIM_ * 2 * DIM_];
__device__ bf s_ffw1T[(size_t)DEPTH_ * 4 * DIM_ * 2 * DIM_];
__device__ bf s_ffw2T[(size_t)DEPTH_ * DIM_ * 2 * 4 * DIM_];
__device__ bf s_logwT[(size_t)VOCAB_ * 2 * DIM_];
__device__ bf s_mwqT[DIM_ * 2 * DIM_];
__device__ bf s_mwkvT[2 * DIM_ * 2 * DIM_];
__device__ bf s_mwoT[DIM_ * 2 * DIM_];
__device__ bf s_posS[HEADS_ * KVLEN_ * 2 * DH_];
__device__ bf s_kvinS[B_ * KVLEN_ * 2 * DIM_];
__device__ bf s_qS[B_ * SEQ_ * 2 * DIM_];
__device__ bf s_kvS[(size_t)B_ * KVLEN_ * 4 * DIM_];
__device__ bf s_vtS[B_ * DIM_ * 2 * KVLEN_];
__device__ bf s_qkS[(size_t)B_ * HEADS_ * SEQ_ * 2 * KVLEN_];
__device__ bf s_aoS[B_ * SEQ_ * 2 * DIM_];
__device__ bf s_ainS[B_ * SEQ_ * 2 * DIM_];
__device__ bf s_ffS[(size_t)B_ * SEQ_ * 2 * 4 * DIM_];
__device__ bf s_hS[B_ * SEQ_ * 2 * DIM_];
__device__ bf s_kvinmS[(size_t)DEPTH_ * B_ * KVLEN_ * 2 * DIM_];
__device__ bf s_ktS[(size_t)DEPTH_ * B_ * DIM_ * 2 * KVLEN_];
__device__ bf s_vtmS[(size_t)DEPTH_ * B_ * DIM_ * 2 * KVLEN_];
__device__ bf s_qmS[DEPTH_ * B_ * LMEM_ * 2 * DIM_];
__device__ bf s_ctxTS[DEPTH_ * B_ * HEADS_ * DH_ * 2 * DH_];
__device__ bf s_outmS[DEPTH_ * B_ * LMEM_ * 2 * DIM_];

// ---------------- helpers ----------------
__device__ __forceinline__ float warpSum(float v) {
    #pragma unroll
    for (int o = 16; o > 0; o >>= 1) v += __shfl_xor_sync(0xffffffffu, v, o);
    return v;
}
__device__ __forceinline__ float warpMax(float v) {
    #pragma unroll
    for (int o = 16; o > 0; o >>= 1) v = fmaxf(v, __shfl_xor_sync(0xffffffffu, v, o));
    return v;
}
__device__ __forceinline__ uint32_t smem_u32(const void* p) {
    uint32_t a;
    asm("{ .reg .u64 t; cvta.to.shared.u64 t, %1; cvt.u32.u64 %0, t; }" : "=r"(a) : "l"(p));
    return a;
}
#define SWZ(x) ((x) ^ (((x) >> 3) & 0x70))
#define LDSM4(r0, r1, r2, r3, addr) \
    asm volatile("ldmatrix.sync.aligned.m8n8.x4.shared.b16 {%0,%1,%2,%3}, [%4];" \
        : "=r"(r0), "=r"(r1), "=r"(r2), "=r"(r3) : "r"(addr))
#define MMA16816(c, a, b) \
    asm volatile("mma.sync.aligned.m16n8k16.row.col.f32.bf16.bf16.f32 " \
        "{%0,%1,%2,%3}, {%4,%5,%6,%7}, {%8,%9}, {%0,%1,%2,%3};" \
        : "+f"((c)[0]), "+f"((c)[1]), "+f"((c)[2]), "+f"((c)[3]) \
        : "r"((a)[0]), "r"((a)[1]), "r"((a)[2]), "r"((a)[3]), "r"((b)[0]), "r"((b)[1]))
__device__ __forceinline__ void splitStore(bf* dst, float vx, float vy) {
    __nv_bfloat162 hh = __floats2bfloat162_rn(vx, vy);
    float2 hf = __bfloat1622float2(hh);
    __nv_bfloat162 ll = __floats2bfloat162_rn(vx - hf.x, vy - hf.y);
    *(__nv_bfloat162*)dst = hh;
    *(__nv_bfloat162*)(dst + 32) = ll;
}

// ---------------- embedding gather ----------------
__global__ void gather_kernel(const int* __restrict__ x, const float* __restrict__ emb,
                              float* __restrict__ h) {
    size_t row = blockIdx.x;
    int tok = x[row];
    ((float4*)(h + row * DIM_))[threadIdx.x] =
        ((const float4*)(emb + (size_t)tok * DIM_))[threadIdx.x];
}

// ---------------- split: fp32 [R][C] rows -> packed [rowOff+r][2C] ----------------
__global__ void split_kernel(const float* __restrict__ src, int srcLd, long srcBS,
                             bf* __restrict__ dst, int dstRowE, long dstBSE,
                             int dstRowOff, int C) {
    int b = blockIdx.z, r = blockIdx.y;
    int c = (blockIdx.x * 256 + threadIdx.x) * 4;
    if (c >= C) return;
    const float4 v = *(const float4*)(src + (size_t)b * srcBS + (size_t)r * srcLd + c);
    bf* o = dst + (size_t)b * dstBSE + (size_t)(dstRowOff + r) * dstRowE + ((c >> 5) * 64 + (c & 31));
    splitStore(o, v.x, v.y);
    splitStore(o + 2, v.z, v.w);
}

// ---------------- transpose+split: fp32 [R][C] -> packed [C][2R] ----------------
__global__ void tsplit_kernel(const float* __restrict__ src, int srcLd, long srcBS,
                              bf* __restrict__ dst, int dstRowE, long dstBSE) {
    __shared__ float t[32][33];
    int b = blockIdx.z;
    const float* s = src + (size_t)b * srcBS;
    int c0 = blockIdx.x * 32, r0 = blockIdx.y * 32;
    int tx = threadIdx.x, ty = threadIdx.y;
    #pragma unroll
    for (int i = 0; i < 4; i++)
        t[ty + 8 * i][tx] = s[(size_t)(r0 + ty + 8 * i) * srcLd + c0 + tx];
    __syncthreads();
    #pragma unroll
    for (int i = 0; i < 4; i++) {
        int cc = ty + 8 * i;
        float v = t[tx][cc];
        bf hb = __float2bfloat16_rn(v);
        bf lb = __float2bfloat16_rn(v - __bfloat162float(hb));
        size_t o = (size_t)b * dstBSE + (size_t)(c0 + cc) * dstRowE + ((r0 >> 5) * 64 + tx);
        dst[o] = hb;
        dst[o + 32] = lb;
    }
}

// ---------------- layernorm -> packed split ----------------
__global__ void layernorm_split_kernel(const float* __restrict__ x, const float* __restrict__ g,
                                       const float* __restrict__ bta, bf* __restrict__ dst,
                                       int rPerB, int dstRowsPerB, int dstRowOff, int dstRowE) {
    const int D = DIM_;
    size_t row = blockIdx.x;
    const float* xr = x + row * D;
    int tid = threadIdx.x, lane = tid & 31, w = tid >> 5;
    float v0 = xr[tid], v1 = xr[tid + 256], v2 = xr[tid + 512], v3 = xr[tid + 768];
    __shared__ float sh[8];
    float s = warpSum(v0 + v1 + v2 + v3);
    if (lane == 0) sh[w] = s;
    __syncthreads();
    if (w == 0) { float t = (lane < 8) ? sh[lane] : 0.f; t = warpSum(t); if (lane == 0) sh[0] = t; }
    __syncthreads();
    float mean = sh[0] * (1.0f / D);
    __syncthreads();
    float d0 = v0 - mean, d1 = v1 - mean, d2 = v2 - mean, d3 = v3 - mean;
    s = warpSum(d0 * d0 + d1 * d1 + d2 * d2 + d3 * d3);
    if (lane == 0) sh[w] = s;
    __syncthreads();
    if (w == 0) { float t = (lane < 8) ? sh[lane] : 0.f; t = warpSum(t); if (lane == 0) sh[0] = t; }
    __syncthreads();
    float rstd = rsqrtf(sh[0] * (1.0f / D) + 1e-5f);
    int bb = (int)(row / rPerB), rl = (int)(row % rPerB);
    bf* yr = dst + ((size_t)bb * dstRowsPerB + dstRowOff + rl) * (size_t)dstRowE;
    float d[4] = {d0, d1, d2, d3};
    #pragma unroll
    for (int qi = 0; qi < 4; qi++) {
        int c = tid + qi * 256;
        float val = d[qi] * rstd;
        if (g) val = val * g[c] + bta[c];
        bf hb = __float2bfloat16_rn(val);
        bf lb = __float2bfloat16_rn(val - __bfloat162float(hb));
        int o = (c >> 5) * 64 + (c & 31);
        yr[o] = hb;
        yr[o + 32] = lb;
    }
}

// ---------------- fused rel-shift + pos-add + mask + softmax -> packed probs ----------------
__global__ void attn_softmax_kernel(const float* __restrict__ S, const float* __restrict__ P,
                                    bf* __restrict__ O) {
    const float scale = 0.08838834764831845f;
    size_t row = blockIdx.x;
    int m = (int)(row & (SEQ_ - 1));
    const float* sr = S + row * (size_t)KVLEN_;
    const float* pr = P + row * (size_t)KVLEN_;
    int tid = threadIdx.x, lane = tid & 31, w = tid >> 5;
    int limit = m + 1280;
    float vals[9];
    float mx = -3.402823466e38f;
    #pragma unroll
    for (int i = 0; i < 9; i++) {
        int n = tid + i * 256;
        float vv = (n <= limit) ? scale * (sr[n] + pr[n + 1023 - m]) : -3.402823466e38f;
        vals[i] = vv;
        mx = fmaxf(mx, vv);
    }
    __shared__ float sh[8];
    float t = warpMax(mx);
    if (lane == 0) sh[w] = t;
    __syncthreads();
    if (w == 0) { float u = (lane < 8) ? sh[lane] : -3.4e38f; u = warpMax(u); if (lane == 0) sh[0] = u; }
    __syncthreads();
    mx = sh[0];
    __syncthreads();
    float s = 0.f;
    #pragma unroll
    for (int i = 0; i < 9; i++) {
        int n = tid + i * 256;
        float e = (n <= limit) ? __expf(vals[i] - mx) : 0.f;
        vals[i] = e;
        s += e;
    }
    t = warpSum(s);
    if (lane == 0) sh[w] = t;
    __syncthreads();
    if (w == 0) { float u = (lane < 8) ? sh[lane] : 0.f; u = warpSum(u); if (lane == 0) sh[0] = u; }
    __syncthreads();
    float inv = 1.0f / sh[0];
    bf* orow = O + row * (size_t)(2 * KVLEN_);
    #pragma unroll
    for (int i = 0; i < 9; i++) {
        int n = tid + i * 256;
        float pv = vals[i] * inv;
        bf hb = __float2bfloat16_rn(pv);
        bf lb = __float2bfloat16_rn(pv - __bfloat162float(hb));
        int o = (n >> 5) * 64 + (n & 31);
        orow[o] = hb;
        orow[o + 32] = lb;
    }
}

// ---------------- per-head softmax over DH=128 (memnet q) ----------------
__global__ void head_softmax_kernel(float* __restrict__ q) {
    const float sc = 0.29730177875068026f;
    float* p = q + (size_t)blockIdx.x * DH_;
    int tid = threadIdx.x, lane = tid & 31, w = tid >> 5;
    float v = p[tid] * sc;
    __shared__ float sh[4];
    float t = warpMax(v);
    if (lane == 0) sh[w] = t;
    __syncthreads();
    float mx = fmaxf(fmaxf(sh[0], sh[1]), fmaxf(sh[2], sh[3]));
    float e = __expf(v - mx);
    __syncthreads();
    t = warpSum(e);
    if (lane == 0) sh[w] = t;
    __syncthreads();
    float s = sh[0] + sh[1] + sh[2] + sh[3];
    p[tid] = e / s;
}

// ---------------- column softmax over n=2304 (memnet k) ----------------
__global__ void col_softmax_kernel(float* __restrict__ kvm) {
    const float sc = 0.29730177875068026f;
    int j = blockIdx.x * 32 + threadIdx.x;
    float* base = kvm + (size_t)blockIdx.y * KVLEN_ * 2048 + j;
    int ty = threadIdx.y;
    float mx = -3.402823466e38f;
    for (int n = ty; n < KVLEN_; n += 8) mx = fmaxf(mx, base[(size_t)n * 2048] * sc);
    __shared__ float sh[8][32];
    sh[ty][threadIdx.x] = mx;
    __syncthreads();
    mx = sh[0][threadIdx.x];
    #pragma unroll
    for (int r = 1; r < 8; r++) mx = fmaxf(mx, sh[r][threadIdx.x]);
    __syncthreads();
    float s = 0.f;
    for (int n = ty; n < KVLEN_; n += 8) s += __expf(base[(size_t)n * 2048] * sc - mx);
    sh[ty][threadIdx.x] = s;
    __syncthreads();
    s = 0.f;
    #pragma unroll
    for (int r = 0; r < 8; r++) s += sh[r][threadIdx.x];
    float inv = 1.0f / s;
    for (int n = ty; n < KVLEN_; n += 8) {
        size_t o = (size_t)n * 2048;
        base[o] = __expf(base[o] * sc - mx) * inv;
    }
}

// ================= GEMM: packed presplit operands, 3-stage cp.async pipeline ================
// A [M][2K] packed bf16, B [N][2K] packed bf16. A/B/Cs strides in bf16 elems; C strides fp32.
// maskMode: 0 none, 1 = QK causal tile skip, 2 = QPE shift-window tile skip, 3 = AV K-cap.
__device__ __forceinline__ void ld_stage(const bf* gA, const bf* gB, long lda, long ldb,
                                         int kt, uint32_t sdst, int tid) {
    int k2 = kt * 64;
    #pragma unroll
    for (int j = 0; j < 4; j++) {
        int i = tid + j * 256;
        int r = i >> 3, c = (i & 7) * 16;
        uint32_t d = SWZ(r * 128 + c);
        const void* pa = gA + (size_t)r * lda + k2 + (i & 7) * 8;
        asm volatile("cp.async.cg.shared.global [%0], [%1], 16;" :: "r"(sdst + d), "l"(pa));
        const void* pb = gB + (size_t)r * ldb + k2 + (i & 7) * 8;
        asm volatile("cp.async.cg.shared.global [%0], [%1], 16;" :: "r"(sdst + 16384 + d), "l"(pb));
    }
}

template <int NPROD>
__global__ void __launch_bounds__(256, 2) gemm_bf16_kernel(
    const bf* __restrict__ A, const bf* __restrict__ B,
    float* __restrict__ C, bf* __restrict__ Cs,
    const float* __restrict__ bias, const float* __restrict__ residual,
    const float* __restrict__ alpha_ptr,
    int K, long lda, long ldb, long ldc, long ldr, long ldcs,
    long sa1, long sa2, long sb1, long sb2, long sc1, long sc2, long scs1, long scs2,
    int b2count, int act, int maskMode) {
    extern __shared__ char smem[];
    uint32_t sbase = smem_u32(smem);
    int tid = threadIdx.x, wid = tid >> 5, lane = tid & 31;
    int bz = blockIdx.z;
    int b1 = bz / b2count, b2 = bz - b1 * b2count;
    int rowBase = blockIdx.x * 128, colBase = blockIdx.y * 128;

    int nkt = K >> 5;
    if (maskMode == 1) {
        if (colBase >= rowBase + 1408) return;          // fully masked: softmax never reads
    } else if (maskMode == 2) {
        if (colBase + 128 <= 896 - rowBase) return;     // below rel-shift read window
    } else if (maskMode == 3) {
        int kl = (rowBase + 1408) >> 5;                 // probs are exact zeros beyond
        if (kl < nkt) nkt = kl;
    }

    const bf* gA = A + (size_t)b1 * sa1 + (size_t)b2 * sa2 + (size_t)rowBase * lda;
    const bf* gB = B + (size_t)b1 * sb1 + (size_t)b2 * sb2 + (size_t)colBase * ldb;

    int wm = (wid & 1) * 64, wn = (wid >> 1) * 32;
    int aRowOff = (wm + (lane & 15)) * 128;
    int bRowOff = (wn + (lane & 15)) * 128;
    int hi16 = (lane >> 4) * 16;
    int xr = (lane & 7) * 16;

    float acc[4][4][4];
    #pragma unroll
    for (int i = 0; i < 4; i++)
        #pragma unroll
        for (int j = 0; j < 4; j++)
            #pragma unroll
            for (int e = 0; e < 4; e++) acc[i][j][e] = 0.f;

    // 3-stage pipeline; one commit per iteration keeps wait_group arithmetic exact
    ld_stage(gA, gB, lda, ldb, 0, sbase, tid);
    asm volatile("cp.async.commit_group;");
    if (nkt > 1) ld_stage(gA, gB, lda, ldb, 1, sbase + 32768, tid);
    asm volatile("cp.async.commit_group;");
    for (int kt = 0; kt < nkt; kt++) {
        if (kt + 2 < nkt)
            ld_stage(gA, gB, lda, ldb, kt + 2, sbase + ((kt + 2) % 3) * 32768, tid);
        asm volatile("cp.async.commit_group;");
        asm volatile("cp.async.wait_group 2;");
        __syncthreads();
        uint32_t sAb = sbase + (kt % 3) * 32768;
        uint32_t sBb = sAb + 16384;
        #pragma unroll
        for (int ks = 0; ks < 2; ks++) {
            int kofH = (ks * 32 + hi16) ^ xr;
            int kofL = (64 + ks * 32 + hi16) ^ xr;
            uint32_t ah[4][4], al[4][4], bb[4][2];
            #pragma unroll
            for (int mi = 0; mi < 4; mi++) {
                uint32_t ad = sAb + aRowOff + mi * 2048;
                LDSM4(ah[mi][0], ah[mi][1], ah[mi][2], ah[mi][3], ad + kofH);
                if (NPROD == 3)
                    LDSM4(al[mi][0], al[mi][1], al[mi][2], al[mi][3], ad + kofL);
            }
            #pragma unroll
            for (int p = 0; p < 2; p++) {
                uint32_t t0, t1, t2, t3;
                LDSM4(t0, t1, t2, t3, sBb + bRowOff + p * 2048 + kofH);
                bb[p * 2][0] = t0; bb[p * 2][1] = t2;
                bb[p * 2 + 1][0] = t1; bb[p * 2 + 1][1] = t3;
            }
            #pragma unroll
            for (int mi = 0; mi < 4; mi++)
                #pragma unroll
                for (int ni = 0; ni < 4; ni++) {
                    MMA16816(acc[mi][ni], ah[mi], bb[ni]);
                    if (NPROD == 3) MMA16816(acc[mi][ni], al[mi], bb[ni]);
                }
            if (NPROD >= 2) {
                #pragma unroll
                for (int p = 0; p < 2; p++) {
                    uint32_t t0, t1, t2, t3;
                    LDSM4(t0, t1, t2, t3, sBb + bRowOff + p * 2048 + kofL);
                    bb[p * 2][0] = t0; bb[p * 2][1] = t2;
                    bb[p * 2 + 1][0] = t1; bb[p * 2 + 1][1] = t3;
                }
                #pragma unroll
                for (int mi = 0; mi < 4; mi++)
                    #pragma unroll
                    for (int ni = 0; ni < 4; ni++)
                        MMA16816(acc[mi][ni], ah[mi], bb[ni]);
            }
        }
        __syncthreads();
    }

    float alpha = alpha_ptr ? *alpha_ptr : 1.0f;
    float* Cb = C ? C + (size_t)b1 * sc1 + (size_t)b2 * sc2 : nullptr;
    bf* Csb = Cs ? Cs + (size_t)b1 * scs1 + (size_t)b2 * scs2 : nullptr;
    int rr = rowBase + wm + (lane >> 2);
    int cc0 = colBase + wn + (lane & 3) * 2;
    #pragma unroll
    for (int mi = 0; mi < 4; mi++) {
        #pragma unroll
        for (int ni = 0; ni < 4; ni++) {
            int gc = cc0 + ni * 8;
            #pragma unroll
            for (int half = 0; half < 2; half++) {
                int gr = rr + mi * 16 + half * 8;
                float2 v = make_float2(acc[mi][ni][half * 2], acc[mi][ni][half * 2 + 1]);
                v.x *= alpha; v.y *= alpha;
                if (bias) {
                    float2 bv = *(const float2*)&bias[gc];
                    v.x += bv.x; v.y += bv.y;
                }
                if (act) {
                    v.x = 0.5f * v.x * (1.0f + erff(v.x * 0.70710678118654752f));
                    v.y = 0.5f * v.y * (1.0f + erff(v.y * 0.70710678118654752f));
                }
                if (residual) {
                    float2 rv = *(const float2*)&residual[(size_t)gr * ldr + gc];
                    v.x += rv.x; v.y += rv.y;
                }
                if (Cb) *(float2*)&Cb[(size_t)gr * ldc + gc] = v;
                if (Csb) splitStore(Csb + (size_t)gr * ldcs + ((gc >> 5) * 64 + (gc & 31)), v.x, v.y);
            }
        }
    }
}

// ---------------- host helpers ----------------
static void gemmx(const bf* A, const bf* B, float* C, bf* Cs,
                  const float* bias, const float* res, const float* alpha,
                  int M, int N, int K, long lda, long ldb, long ldc, long ldr, long ldcs,
                  long sa1, long sa2, long sb1, long sb2, long sc1, long sc2, long scs1, long scs2,
                  int b1c, int b2c, int act, int nprod, int maskMode) {
    dim3 grid(M / 128, N / 128, b1c * b2c);
    if (nprod == 1) {
        cudaFuncSetAttribute(gemm_bf16_kernel<1>, cudaFuncAttributeMaxDynamicSharedMemorySize, 98304);
        gemm_bf16_kernel<1><<<grid, 256, 98304>>>(A, B, C, Cs, bias, res, alpha, K,
                                                  lda, ldb, ldc, ldr, ldcs,
                                                  sa1, sa2, sb1, sb2, sc1, sc2, scs1, scs2,
                                                  b2c, act, maskMode);
    } else {
        cudaFuncSetAttribute(gemm_bf16_kernel<3>, cudaFuncAttributeMaxDynamicSharedMemorySize, 98304);
        gemm_bf16_kernel<3><<<grid, 256, 98304>>>(A, B, C, Cs, bias, res, alpha, K,
                                                  lda, ldb, ldc, ldr, ldcs,
                                                  sa1, sa2, sb1, sb2, sc1, sc2, scs1, scs2,
                                                  b2c, act, maskMode);
    }
}
static void splitx(const float* src, int srcLd, long srcBS, bf* dst, int dstRowE,
                   long dstBSE, int dstRowOff, int R, int C, int nb) {
    dim3 grid((C + 1023) / 1024, R, nb);
    split_kernel<<<grid, 256>>>(src, srcLd, srcBS, dst, dstRowE, dstBSE, dstRowOff, C);
}
static void tsplitx(const float* src, int srcLd, long srcBS, bf* dst, int dstRowE,
                    long dstBSE, int R, int C, int nb) {
    dim3 grid(C / 32, R / 32, nb);
    tsplit_kernel<<<grid, dim3(32, 8)>>>(src, srcLd, srcBS, dst, dstRowE, dstBSE);
}
template <typename T>
static T* symp(const void* s) {
    void* p = nullptr;
    cudaGetSymbolAddress(&p, s);
    return (T*)p;
}

extern "C" void kernel_launch(void* const* d_in, const int* in_sizes, int n_in,
                              void* d_out, int out_size) {
    const int*   x         = (const int*)d_in[0];
    const float* mem       = (const float*)d_in[1];
    const float* lmem      = (const float*)d_in[2];
    const float* token_emb = (const float*)d_in[3];
    const float* pos_emb   = (const float*)d_in[4];
    const float* attn_ln_g = (const float*)d_in[5];
    const float* attn_ln_b = (const float*)d_in[6];
    const float* attn_wq   = (const float*)d_in[7];
    const float* attn_wkv  = (const float*)d_in[8];
    const float* attn_wo   = (const float*)d_in[9];
    const float* attn_bo   = (const float*)d_in[10];
    const float* ff_ln_g   = (const float*)d_in[11];
    const float* ff_ln_b   = (const float*)d_in[12];
    const float* ff_w1     = (const float*)d_in[13];
    const float* ff_b1     = (const float*)d_in[14];
    const float* ff_w2     = (const float*)d_in[15];
    const float* ff_b2     = (const float*)d_in[16];
    const float* logits_w  = (const float*)d_in[17];
    const float* logits_b  = (const float*)d_in[18];
    const float* mem_wq    = (const float*)d_in[19];
    const float* mem_wkv   = (const float*)d_in[20];
    const float* mem_wo    = (const float*)d_in[21];
    const float* rezero    = (const float*)d_in[22];

    float* out        = (float*)d_out;
    float* out_logits = out;
    float* out_mem    = out + (size_t)B_ * SEQ_ * VOCAB_;
    float* out_lmem   = out_mem + (size_t)DEPTH_ * B_ * SEQ_ * DIM_;

    float* h    = symp<float>(g_h);
    float* kv   = symp<float>(g_kv);
    float* qk   = symp<float>(g_qk);
    float* qp   = symp<float>(g_qp);
    float* kvm  = symp<float>(g_kvm);
    float* qm   = symp<float>(g_qm);
    float* ctx  = symp<float>(g_ctx);
    bf* wqT   = symp<bf>(s_wqT);
    bf* wkvT  = symp<bf>(s_wkvT);
    bf* woT   = symp<bf>(s_woT);
    bf* ffw1T = symp<bf>(s_ffw1T);
    bf* ffw2T = symp<bf>(s_ffw2T);
    bf* logwT = symp<bf>(s_logwT);
    bf* mwqT  = symp<bf>(s_mwqT);
    bf* mwkvT = symp<bf>(s_mwkvT);
    bf* mwoT  = symp<bf>(s_mwoT);
    bf* posS  = symp<bf>(s_posS);
    bf* kvinS = symp<bf>(s_kvinS);
    bf* qS    = symp<bf>(s_qS);
    bf* kvS   = symp<bf>(s_kvS);
    bf* vtS   = symp<bf>(s_vtS);
    bf* qkS   = symp<bf>(s_qkS);
    bf* aoS   = symp<bf>(s_aoS);
    bf* ainS  = symp<bf>(s_ainS);
    bf* ffS   = symp<bf>(s_ffS);
    bf* hS    = symp<bf>(s_hS);
    bf* kvinmS = symp<bf>(s_kvinmS);
    bf* ktS    = symp<bf>(s_ktS);
    bf* vtmS   = symp<bf>(s_vtmS);
    bf* qmS    = symp<bf>(s_qmS);
    bf* ctxTS  = symp<bf>(s_ctxTS);
    bf* outmS  = symp<bf>(s_outmS);

    const size_t rowBytes = sizeof(float) * DIM_;

    // ---- weight / pos transposes+splits ----
    tsplitx(attn_wq, DIM_, (long)DIM_ * DIM_, wqT, 2 * DIM_, (long)DIM_ * 2 * DIM_, DIM_, DIM_, DEPTH_);
    tsplitx(attn_wkv, 2 * DIM_, (long)DIM_ * 2 * DIM_, wkvT, 2 * DIM_, (long)2 * DIM_ * 2 * DIM_, DIM_, 2 * DIM_, DEPTH_);
    tsplitx(attn_wo, DIM_, (long)DIM_ * DIM_, woT, 2 * DIM_, (long)DIM_ * 2 * DIM_, DIM_, DIM_, DEPTH_);
    tsplitx(ff_w1, 4 * DIM_, (long)DIM_ * 4 * DIM_, ffw1T, 2 * DIM_, (long)4 * DIM_ * 2 * DIM_, DIM_, 4 * DIM_, DEPTH_);
    tsplitx(ff_w2, DIM_, (long)4 * DIM_ * DIM_, ffw2T, 8 * DIM_, (long)DIM_ * 8 * DIM_, 4 * DIM_, DIM_, DEPTH_);
    tsplitx(logits_w, VOCAB_, 0, logwT, 2 * DIM_, 0, DIM_, VOCAB_, 1);
    tsplitx(mem_wq, DIM_, 0, mwqT, 2 * DIM_, 0, DIM_, DIM_, 1);
    tsplitx(mem_wkv, 2 * DIM_, 0, mwkvT, 2 * DIM_, 0, DIM_, 2 * DIM_, 1);
    tsplitx(mem_wo, DIM_, 0, mwoT, 2 * DIM_, 0, DIM_, DIM_, 1);
    splitx(pos_emb, DH_, 0, posS, 2 * DH_, 0, 0, HEADS_ * KVLEN_, DH_, 1);

    gather_kernel<<<B_ * SEQ_, 256>>>(x, token_emb, h);

    for (int l = 0; l < DEPTH_; l++) {
        cudaMemcpyAsync(out_mem + (size_t)l * B_ * SEQ_ * DIM_, h,
                        (size_t)B_ * SEQ_ * rowBytes, cudaMemcpyDeviceToDevice, 0);
        layernorm_split_kernel<<<B_ * SEQ_, 256>>>(h, attn_ln_g + l * DIM_, attn_ln_b + l * DIM_,
                                                   kvinS, SEQ_, KVLEN_, LMEM_ + MEM_, 2 * DIM_);
        splitx(lmem + (size_t)l * B_ * LMEM_ * DIM_, DIM_, (long)LMEM_ * DIM_,
               kvinS, 2 * DIM_, (long)KVLEN_ * 2 * DIM_, 0, LMEM_, DIM_, B_);
        splitx(mem + (size_t)l * B_ * MEM_ * DIM_, DIM_, (long)MEM_ * DIM_,
               kvinS, 2 * DIM_, (long)KVLEN_ * 2 * DIM_, LMEM_, MEM_, DIM_, B_);
        // q = a_in @ wq -> qS
        gemmx(kvinS + (size_t)(LMEM_ + MEM_) * 2 * DIM_, wqT + (size_t)l * DIM_ * 2 * DIM_,
              nullptr, qS, nullptr, nullptr, nullptr,
              SEQ_, DIM_, DIM_, 2 * DIM_, 2 * DIM_, 0, 0, 2 * DIM_,
              (long)KVLEN_ * 2 * DIM_, 0, 0, 0, 0, 0, (long)SEQ_ * 2 * DIM_, 0, B_, 1, 0, 3, 0);
        // kv = kv_in @ wkv -> kv (fp32) + kvS
        gemmx(kvinS, wkvT + (size_t)l * 2 * DIM_ * 2 * DIM_, kv, kvS, nullptr, nullptr, nullptr,
              KVLEN_, 2 * DIM_, DIM_, 2 * DIM_, 2 * DIM_, 2 * DIM_, 0, 4 * DIM_,
              (long)KVLEN_ * 2 * DIM_, 0, 0, 0, (long)KVLEN_ * 2 * DIM_, 0,
              (long)KVLEN_ * 4 * DIM_, 0, B_, 1, 0, 3, 0);
        // vt = transpose(V half)
        tsplitx(kv + DIM_, 2 * DIM_, (long)KVLEN_ * 2 * DIM_, vtS, 2 * KVLEN_,
                (long)DIM_ * 2 * KVLEN_, KVLEN_, DIM_, B_);
        // QK^T (causal tile skip)
        gemmx(qS, kvS, qk, nullptr, nullptr, nullptr, nullptr,
              SEQ_, KVLEN_, DH_, 2 * DIM_, 4 * DIM_, KVLEN_, 0, 0,
              (long)SEQ_ * 2 * DIM_, 256, (long)KVLEN_ * 4 * DIM_, 256,
              (long)HEADS_ * SEQ_ * KVLEN_, (long)SEQ_ * KVLEN_, 0, 0, B_, HEADS_, 0, 3, 1);
        // Q PE^T (single product; shift-window tile skip)
        gemmx(qS, posS, qp, nullptr, nullptr, nullptr, nullptr,
              SEQ_, KVLEN_, DH_, 2 * DIM_, 2 * DH_, KVLEN_, 0, 0,
              (long)SEQ_ * 2 * DIM_, 256, 0, (long)KVLEN_ * 2 * DH_,
              (long)HEADS_ * SEQ_ * KVLEN_, (long)SEQ_ * KVLEN_, 0, 0, B_, HEADS_, 0, 1, 2);
        attn_softmax_kernel<<<B_ * HEADS_ * SEQ_, 256>>>(qk, qp, qkS);
        // attn @ V -> aoS (K capped per row tile)
        gemmx(qkS, vtS, nullptr, aoS, nullptr, nullptr, nullptr,
              SEQ_, DH_, KVLEN_, 2 * KVLEN_, 2 * KVLEN_, 0, 0, 2 * DIM_,
              (long)HEADS_ * SEQ_ * 2 * KVLEN_, (long)SEQ_ * 2 * KVLEN_,
              (long)DIM_ * 2 * KVLEN_, (long)DH_ * 2 * KVLEN_,
              0, 0, (long)SEQ_ * 2 * DIM_, 256, B_, HEADS_, 0, 3, 3);
        // h += ao @ wo + bo
        gemmx(aoS, woT + (size_t)l * DIM_ * 2 * DIM_, h, nullptr,
              attn_bo + l * DIM_, h, nullptr,
              B_ * SEQ_, DIM_, DIM_, 2 * DIM_, 2 * DIM_, DIM_, DIM_, 0,
              0, 0, 0, 0, 0, 0, 0, 0, 1, 1, 0, 3, 0);
        // FF
        layernorm_split_kernel<<<B_ * SEQ_, 256>>>(h, ff_ln_g + l * DIM_, ff_ln_b + l * DIM_,
                                                   ainS, B_ * SEQ_, 0, 0, 2 * DIM_);
        gemmx(ainS, ffw1T + (size_t)l * 4 * DIM_ * 2 * DIM_, nullptr, ffS,
              ff_b1 + (size_t)l * 4 * DIM_, nullptr, nullptr,
              B_ * SEQ_, 4 * DIM_, DIM_, 2 * DIM_, 2 * DIM_, 0, 0, 8 * DIM_,
              0, 0, 0, 0, 0, 0, 0, 0, 1, 1, 1, 3, 0);
        gemmx(ffS, ffw2T + (size_t)l * DIM_ * 8 * DIM_, h, hS,
              ff_b2 + l * DIM_, h, nullptr,
              B_ * SEQ_, DIM_, 4 * DIM_, 8 * DIM_, 8 * DIM_, DIM_, DIM_, 2 * DIM_,
              0, 0, 0, 0, 0, 0, 0, 0, 1, 1, 0, 3, 0);
    }

    // logits
    gemmx(hS, logwT, out_logits, nullptr, logits_b, nullptr, nullptr,
          B_ * SEQ_, VOCAB_, DIM_, 2 * DIM_, 2 * DIM_, VOCAB_, 0, 0,
          0, 0, 0, 0, 0, 0, 0, 0, 1, 1, 0, 3, 0);

    // ---------------- memory network ----------------
    layernorm_split_kernel<<<DEPTH_ * B_ * LMEM_, 256>>>(lmem, nullptr, nullptr,
                                                         kvinmS, LMEM_, KVLEN_, 0, 2 * DIM_);
    splitx(mem, DIM_, (long)MEM_ * DIM_, kvinmS, 2 * DIM_, (long)KVLEN_ * 2 * DIM_,
           LMEM_, MEM_, DIM_, DEPTH_ * B_);
    splitx(out_mem, DIM_, (long)SEQ_ * DIM_, kvinmS, 2 * DIM_, (long)KVLEN_ * 2 * DIM_,
           LMEM_ + MEM_, SEQ_, DIM_, DEPTH_ * B_);
    // qm = nl @ wq
    gemmx(kvinmS, mwqT, qm, nullptr, nullptr, nullptr, nullptr,
          LMEM_, DIM_, DIM_, 2 * DIM_, 2 * DIM_, DIM_, 0, 0,
          (long)KVLEN_ * 2 * DIM_, 0, 0, 0, (long)LMEM_ * DIM_, 0, 0, 0, DEPTH_ * B_, 1, 0, 3, 0);
    head_softmax_kernel<<<DEPTH_ * B_ * LMEM_ * HEADS_, 128>>>(qm);
    splitx(qm, DIM_, (long)LMEM_ * DIM_, qmS, 2 * DIM_, (long)LMEM_ * 2 * DIM_,
           0, LMEM_, DIM_, DEPTH_ * B_);
    // kvm = kvinm @ wkv
    gemmx(kvinmS, mwkvT, kvm, nullptr, nullptr, nullptr, nullptr,
          KVLEN_, 2 * DIM_, DIM_, 2 * DIM_, 2 * DIM_, 2 * DIM_, 0, 0,
          (long)KVLEN_ * 2 * DIM_, 0, 0, 0, (long)KVLEN_ * 2 * DIM_, 0, 0, 0, DEPTH_ * B_, 1, 0, 3, 0);
    col_softmax_kernel<<<dim3(32, DEPTH_ * B_), dim3(32, 8)>>>(kvm);
    tsplitx(kvm, 2 * DIM_, (long)KVLEN_ * 2 * DIM_, ktS, 2 * KVLEN_,
            (long)DIM_ * 2 * KVLEN_, KVLEN_, DIM_, DEPTH_ * B_);
    tsplitx(kvm + DIM_, 2 * DIM_, (long)KVLEN_ * 2 * DIM_, vtmS, 2 * KVLEN_,
            (long)DIM_ * 2 * KVLEN_, KVLEN_, DIM_, DEPTH_ * B_);
    // ctx = k^T v
    gemmx(ktS, vtmS, ctx, nullptr, nullptr, nullptr, nullptr,
          DH_, DH_, KVLEN_, 2 * KVLEN_, 2 * KVLEN_, DH_, 0, 0,
          (long)DIM_ * 2 * KVLEN_, (long)DH_ * 2 * KVLEN_,
          (long)DIM_ * 2 * KVLEN_, (long)DH_ * 2 * KVLEN_,
          (long)HEADS_ * DH_ * DH_, (long)DH_ * DH_, 0, 0, DEPTH_ * B_, HEADS_, 0, 3, 0);
    tsplitx(ctx, DH_, (long)DH_ * DH_, ctxTS, 2 * DH_, (long)DH_ * 2 * DH_,
            DH_, DH_, DEPTH_ * B_ * HEADS_);
    // outm = q @ ctx -> outmS
    gemmx(qmS, ctxTS, nullptr, outmS, nullptr, nullptr, nullptr,
          LMEM_, DH_, DH_, 2 * DIM_, 2 * DH_, 0, 0, 2 * DIM_,
          (long)LMEM_ * 2 * DIM_, 256, (long)HEADS_ * DH_ * 2 * DH_, (long)DH_ * 2 * DH_,
          0, 0, (long)LMEM_ * 2 * DIM_, 256, DEPTH_ * B_, HEADS_, 0, 3, 0);
    // next_lmem = rezero*(outm @ wo) + lmem
    gemmx(outmS, mwoT, out_lmem, nullptr, nullptr, lmem, rezero,
          DEPTH_ * B_ * LMEM_, DIM_, DIM_, 2 * DIM_, 2 * DIM_, DIM_, DIM_, 0,
          0, 0, 0, 0, 0, 0, 0, 0, 1, 1, 0, 3, 0);
}

// round 13
// speedup vs baseline: 1.5392x; 1.5392x over previous
#include <cuda_runtime.h>
#include <cuda_bf16.h>
#include <math.h>
#include <stdint.h>

#define B_ 2
#define DEPTH_ 4
#define HEADS_ 8
#define DIM_ 1024
#define DH_ 128
#define SEQ_ 1024
#define MEM_ 1024
#define LMEM_ 256
#define VOCAB_ 32000
#define KVLEN_ (LMEM_ + MEM_ + SEQ_)   // 2304
typedef __nv_bfloat16 bf;

// ---------------- fp32 scratch ----------------
__device__ float g_h[B_ * SEQ_ * DIM_];
__device__ float g_kv[B_ * KVLEN_ * 2 * DIM_];
__device__ float g_qk[(size_t)B_ * HEADS_ * SEQ_ * KVLEN_];
__device__ float g_qp[(size_t)B_ * HEADS_ * SEQ_ * KVLEN_];
__device__ float g_kvm[(size_t)DEPTH_ * B_ * KVLEN_ * 2 * DIM_];
__device__ float g_qm[DEPTH_ * B_ * LMEM_ * DIM_];
__device__ float g_ctx[DEPTH_ * B_ * HEADS_ * DH_ * DH_];

// ---------------- packed bf16 hi/lo scratch (per 32 logical cols: 32 hi | 32 lo) ----------------
__device__ bf s_wqT[DEPTH_ * DIM_ * 2 * DIM_];
__device__ bf s_wkvT[(size_t)DEPTH_ * 2 * DIM_ * 2 * DIM_];
__device__ bf s_woT[DEPTH_ * DIM_ * 2 * DIM_];
__device__ bf s_ffw1T[(size_t)DEPTH_ * 4 * DIM_ * 2 * DIM_];
__device__ bf s_ffw2T[(size_t)DEPTH_ * DIM_ * 2 * 4 * DIM_];
__device__ bf s_logwT[(size_t)VOCAB_ * 2 * DIM_];
__device__ bf s_mwqT[DIM_ * 2 * DIM_];
__device__ bf s_mwkvT[2 * DIM_ * 2 * DIM_];
__device__ bf s_mwoT[DIM_ * 2 * DIM_];
__device__ bf s_posS[HEADS_ * KVLEN_ * 2 * DH_];
__device__ bf s_kvinS[B_ * KVLEN_ * 2 * DIM_];
__device__ bf s_qS[B_ * SEQ_ * 2 * DIM_];
__device__ bf s_kvS[(size_t)B_ * KVLEN_ * 4 * DIM_];
__device__ bf s_vtS[B_ * DIM_ * 2 * KVLEN_];
__device__ bf s_qkS[(size_t)B_ * HEADS_ * SEQ_ * 2 * KVLEN_];
__device__ bf s_aoS[B_ * SEQ_ * 2 * DIM_];
__device__ bf s_ainS[B_ * SEQ_ * 2 * DIM_];
__device__ bf s_ffS[(size_t)B_ * SEQ_ * 2 * 4 * DIM_];
__device__ bf s_hS[B_ * SEQ_ * 2 * DIM_];
__device__ bf s_kvinmS[(size_t)DEPTH_ * B_ * KVLEN_ * 2 * DIM_];
__device__ bf s_ktS[(size_t)DEPTH_ * B_ * DIM_ * 2 * KVLEN_];
__device__ bf s_vtmS[(size_t)DEPTH_ * B_ * DIM_ * 2 * KVLEN_];
__device__ bf s_qmS[DEPTH_ * B_ * LMEM_ * 2 * DIM_];
__device__ bf s_ctxTS[DEPTH_ * B_ * HEADS_ * DH_ * 2 * DH_];
__device__ bf s_outmS[DEPTH_ * B_ * LMEM_ * 2 * DIM_];

// ---------------- helpers ----------------
__device__ __forceinline__ float warpSum(float v) {
    #pragma unroll
    for (int o = 16; o > 0; o >>= 1) v += __shfl_xor_sync(0xffffffffu, v, o);
    return v;
}
__device__ __forceinline__ float warpMax(float v) {
    #pragma unroll
    for (int o = 16; o > 0; o >>= 1) v = fmaxf(v, __shfl_xor_sync(0xffffffffu, v, o));
    return v;
}
__device__ __forceinline__ uint32_t smem_u32(const void* p) {
    uint32_t a;
    asm("{ .reg .u64 t; cvta.to.shared.u64 t, %1; cvt.u32.u64 %0, t; }" : "=r"(a) : "l"(p));
    return a;
}
#define SWZ(x) ((x) ^ (((x) >> 3) & 0x70))
#define LDSM4(r0, r1, r2, r3, addr) \
    asm volatile("ldmatrix.sync.aligned.m8n8.x4.shared.b16 {%0,%1,%2,%3}, [%4];" \
        : "=r"(r0), "=r"(r1), "=r"(r2), "=r"(r3) : "r"(addr))
#define MMA16816(c, a, b) \
    asm volatile("mma.sync.aligned.m16n8k16.row.col.f32.bf16.bf16.f32 " \
        "{%0,%1,%2,%3}, {%4,%5,%6,%7}, {%8,%9}, {%0,%1,%2,%3};" \
        : "+f"((c)[0]), "+f"((c)[1]), "+f"((c)[2]), "+f"((c)[3]) \
        : "r"((a)[0]), "r"((a)[1]), "r"((a)[2]), "r"((a)[3]), "r"((b)[0]), "r"((b)[1]))
__device__ __forceinline__ void splitStore(bf* dst, float vx, float vy) {
    __nv_bfloat162 hh = __floats2bfloat162_rn(vx, vy);
    float2 hf = __bfloat1622float2(hh);
    __nv_bfloat162 ll = __floats2bfloat162_rn(vx - hf.x, vy - hf.y);
    *(__nv_bfloat162*)dst = hh;
    *(__nv_bfloat162*)(dst + 32) = ll;
}

// ---------------- embedding gather ----------------
__global__ void gather_kernel(const int* __restrict__ x, const float* __restrict__ emb,
                              float* __restrict__ h) {
    size_t row = blockIdx.x;
    int tok = x[row];
    ((float4*)(h + row * DIM_))[threadIdx.x] =
        ((const float4*)(emb + (size_t)tok * DIM_))[threadIdx.x];
}

// ---------------- split: fp32 [R][C] rows -> packed [rowOff+r][2C] ----------------
__global__ void split_kernel(const float* __restrict__ src, int srcLd, long srcBS,
                             bf* __restrict__ dst, int dstRowE, long dstBSE,
                             int dstRowOff, int C) {
    int b = blockIdx.z, r = blockIdx.y;
    int c = (blockIdx.x * 256 + threadIdx.x) * 4;
    if (c >= C) return;
    const float4 v = *(const float4*)(src + (size_t)b * srcBS + (size_t)r * srcLd + c);
    bf* o = dst + (size_t)b * dstBSE + (size_t)(dstRowOff + r) * dstRowE + ((c >> 5) * 64 + (c & 31));
    splitStore(o, v.x, v.y);
    splitStore(o + 2, v.z, v.w);
}

// ---------------- transpose+split: fp32 [R][C] -> packed [C][2R] ----------------
__global__ void tsplit_kernel(const float* __restrict__ src, int srcLd, long srcBS,
                              bf* __restrict__ dst, int dstRowE, long dstBSE) {
    __shared__ float t[32][33];
    int b = blockIdx.z;
    const float* s = src + (size_t)b * srcBS;
    int c0 = blockIdx.x * 32, r0 = blockIdx.y * 32;
    int tx = threadIdx.x, ty = threadIdx.y;
    #pragma unroll
    for (int i = 0; i < 4; i++)
        t[ty + 8 * i][tx] = s[(size_t)(r0 + ty + 8 * i) * srcLd + c0 + tx];
    __syncthreads();
    #pragma unroll
    for (int i = 0; i < 4; i++) {
        int cc = ty + 8 * i;
        float v = t[tx][cc];
        bf hb = __float2bfloat16_rn(v);
        bf lb = __float2bfloat16_rn(v - __bfloat162float(hb));
        size_t o = (size_t)b * dstBSE + (size_t)(c0 + cc) * dstRowE + ((r0 >> 5) * 64 + tx);
        dst[o] = hb;
        dst[o + 32] = lb;
    }
}

// ---------------- layernorm -> packed split ----------------
__global__ void layernorm_split_kernel(const float* __restrict__ x, const float* __restrict__ g,
                                       const float* __restrict__ bta, bf* __restrict__ dst,
                                       int rPerB, int dstRowsPerB, int dstRowOff, int dstRowE) {
    const int D = DIM_;
    size_t row = blockIdx.x;
    const float* xr = x + row * D;
    int tid = threadIdx.x, lane = tid & 31, w = tid >> 5;
    float v0 = xr[tid], v1 = xr[tid + 256], v2 = xr[tid + 512], v3 = xr[tid + 768];
    __shared__ float sh[8];
    float s = warpSum(v0 + v1 + v2 + v3);
    if (lane == 0) sh[w] = s;
    __syncthreads();
    if (w == 0) { float t = (lane < 8) ? sh[lane] : 0.f; t = warpSum(t); if (lane == 0) sh[0] = t; }
    __syncthreads();
    float mean = sh[0] * (1.0f / D);
    __syncthreads();
    float d0 = v0 - mean, d1 = v1 - mean, d2 = v2 - mean, d3 = v3 - mean;
    s = warpSum(d0 * d0 + d1 * d1 + d2 * d2 + d3 * d3);
    if (lane == 0) sh[w] = s;
    __syncthreads();
    if (w == 0) { float t = (lane < 8) ? sh[lane] : 0.f; t = warpSum(t); if (lane == 0) sh[0] = t; }
    __syncthreads();
    float rstd = rsqrtf(sh[0] * (1.0f / D) + 1e-5f);
    int bb = (int)(row / rPerB), rl = (int)(row % rPerB);
    bf* yr = dst + ((size_t)bb * dstRowsPerB + dstRowOff + rl) * (size_t)dstRowE;
    float d[4] = {d0, d1, d2, d3};
    #pragma unroll
    for (int qi = 0; qi < 4; qi++) {
        int c = tid + qi * 256;
        float val = d[qi] * rstd;
        if (g) val = val * g[c] + bta[c];
        bf hb = __float2bfloat16_rn(val);
        bf lb = __float2bfloat16_rn(val - __bfloat162float(hb));
        int o = (c >> 5) * 64 + (c & 31);
        yr[o] = hb;
        yr[o + 32] = lb;
    }
}

// ---------------- fused rel-shift + pos-add + mask + softmax -> packed probs ----------------
__global__ void attn_softmax_kernel(const float* __restrict__ S, const float* __restrict__ P,
                                    bf* __restrict__ O) {
    const float scale = 0.08838834764831845f;
    size_t row = blockIdx.x;
    int m = (int)(row & (SEQ_ - 1));
    const float* sr = S + row * (size_t)KVLEN_;
    const float* pr = P + row * (size_t)KVLEN_;
    int tid = threadIdx.x, lane = tid & 31, w = tid >> 5;
    int limit = m + 1280;
    float vals[9];
    float mx = -3.402823466e38f;
    #pragma unroll
    for (int i = 0; i < 9; i++) {
        int n = tid + i * 256;
        float vv = (n <= limit) ? scale * (sr[n] + pr[n + 1023 - m]) : -3.402823466e38f;
        vals[i] = vv;
        mx = fmaxf(mx, vv);
    }
    __shared__ float sh[8];
    float t = warpMax(mx);
    if (lane == 0) sh[w] = t;
    __syncthreads();
    if (w == 0) { float u = (lane < 8) ? sh[lane] : -3.4e38f; u = warpMax(u); if (lane == 0) sh[0] = u; }
    __syncthreads();
    mx = sh[0];
    __syncthreads();
    float s = 0.f;
    #pragma unroll
    for (int i = 0; i < 9; i++) {
        int n = tid + i * 256;
        float e = (n <= limit) ? __expf(vals[i] - mx) : 0.f;
        vals[i] = e;
        s += e;
    }
    t = warpSum(s);
    if (lane == 0) sh[w] = t;
    __syncthreads();
    if (w == 0) { float u = (lane < 8) ? sh[lane] : 0.f; u = warpSum(u); if (lane == 0) sh[0] = u; }
    __syncthreads();
    float inv = 1.0f / sh[0];
    bf* orow = O + row * (size_t)(2 * KVLEN_);
    #pragma unroll
    for (int i = 0; i < 9; i++) {
        int n = tid + i * 256;
        float pv = vals[i] * inv;
        bf hb = __float2bfloat16_rn(pv);
        bf lb = __float2bfloat16_rn(pv - __bfloat162float(hb));
        int o = (n >> 5) * 64 + (n & 31);
        orow[o] = hb;
        orow[o + 32] = lb;
    }
}

// ---------------- per-head softmax over DH=128 (memnet q) ----------------
__global__ void head_softmax_kernel(float* __restrict__ q) {
    const float sc = 0.29730177875068026f;
    float* p = q + (size_t)blockIdx.x * DH_;
    int tid = threadIdx.x, lane = tid & 31, w = tid >> 5;
    float v = p[tid] * sc;
    __shared__ float sh[4];
    float t = warpMax(v);
    if (lane == 0) sh[w] = t;
    __syncthreads();
    float mx = fmaxf(fmaxf(sh[0], sh[1]), fmaxf(sh[2], sh[3]));
    float e = __expf(v - mx);
    __syncthreads();
    t = warpSum(e);
    if (lane == 0) sh[w] = t;
    __syncthreads();
    float s = sh[0] + sh[1] + sh[2] + sh[3];
    p[tid] = e / s;
}

// ---------------- column softmax over n=2304 (memnet k) ----------------
__global__ void col_softmax_kernel(float* __restrict__ kvm) {
    const float sc = 0.29730177875068026f;
    int j = blockIdx.x * 32 + threadIdx.x;
    float* base = kvm + (size_t)blockIdx.y * KVLEN_ * 2048 + j;
    int ty = threadIdx.y;
    float mx = -3.402823466e38f;
    for (int n = ty; n < KVLEN_; n += 8) mx = fmaxf(mx, base[(size_t)n * 2048] * sc);
    __shared__ float sh[8][32];
    sh[ty][threadIdx.x] = mx;
    __syncthreads();
    mx = sh[0][threadIdx.x];
    #pragma unroll
    for (int r = 1; r < 8; r++) mx = fmaxf(mx, sh[r][threadIdx.x]);
    __syncthreads();
    float s = 0.f;
    for (int n = ty; n < KVLEN_; n += 8) s += __expf(base[(size_t)n * 2048] * sc - mx);
    sh[ty][threadIdx.x] = s;
    __syncthreads();
    s = 0.f;
    #pragma unroll
    for (int r = 0; r < 8; r++) s += sh[r][threadIdx.x];
    float inv = 1.0f / s;
    for (int n = ty; n < KVLEN_; n += 8) {
        size_t o = (size_t)n * 2048;
        base[o] = __expf(base[o] * sc - mx) * inv;
    }
}

// ================= GEMM: packed presplit operands, 2-stage cp.async (64KB, 2 CTAs/SM) =======
// A [M][2K] packed bf16, B [N][2K] packed bf16. A/B/Cs strides in bf16 elems; C strides fp32.
// maskMode: 0 none, 1 = QK causal tile skip, 2 = QPE shift-window tile skip, 3 = AV K-cap.
__device__ __forceinline__ void ld_stage(const bf* gA, const bf* gB, long lda, long ldb,
                                         int kt, uint32_t sdst, int tid) {
    int k2 = kt * 64;
    #pragma unroll
    for (int j = 0; j < 4; j++) {
        int i = tid + j * 256;
        int r = i >> 3, c = (i & 7) * 16;
        uint32_t d = SWZ(r * 128 + c);
        const void* pa = gA + (size_t)r * lda + k2 + (i & 7) * 8;
        asm volatile("cp.async.cg.shared.global [%0], [%1], 16;" :: "r"(sdst + d), "l"(pa));
        const void* pb = gB + (size_t)r * ldb + k2 + (i & 7) * 8;
        asm volatile("cp.async.cg.shared.global [%0], [%1], 16;" :: "r"(sdst + 16384 + d), "l"(pb));
    }
}

template <int NPROD>
__global__ void __launch_bounds__(256, 2) gemm_bf16_kernel(
    const bf* __restrict__ A, const bf* __restrict__ B,
    float* __restrict__ C, bf* __restrict__ Cs,
    const float* __restrict__ bias, const float* __restrict__ residual,
    const float* __restrict__ alpha_ptr,
    int K, long lda, long ldb, long ldc, long ldr, long ldcs,
    long sa1, long sa2, long sb1, long sb2, long sc1, long sc2, long scs1, long scs2,
    int b2count, int act, int maskMode) {
    extern __shared__ char smem[];
    uint32_t sbase = smem_u32(smem);
    int tid = threadIdx.x, wid = tid >> 5, lane = tid & 31;
    int bz = blockIdx.z;
    int b1 = bz / b2count, b2 = bz - b1 * b2count;
    int rowBase = blockIdx.x * 128, colBase = blockIdx.y * 128;

    int nkt = K >> 5;
    if (maskMode == 1) {
        if (colBase >= rowBase + 1408) return;          // fully masked: softmax never reads
    } else if (maskMode == 2) {
        if (colBase + 128 <= 896 - rowBase) return;     // below rel-shift read window
    } else if (maskMode == 3) {
        int kl = (rowBase + 1408) >> 5;                 // probs are exact zeros beyond
        if (kl < nkt) nkt = kl;
    }

    const bf* gA = A + (size_t)b1 * sa1 + (size_t)b2 * sa2 + (size_t)rowBase * lda;
    const bf* gB = B + (size_t)b1 * sb1 + (size_t)b2 * sb2 + (size_t)colBase * ldb;

    int wm = (wid & 1) * 64, wn = (wid >> 1) * 32;
    int aRowOff = (wm + (lane & 15)) * 128;
    int bRowOff = (wn + (lane & 15)) * 128;
    int hi16 = (lane >> 4) * 16;
    int xr = (lane & 7) * 16;

    float acc[4][4][4];
    #pragma unroll
    for (int i = 0; i < 4; i++)
        #pragma unroll
        for (int j = 0; j < 4; j++)
            #pragma unroll
            for (int e = 0; e < 4; e++) acc[i][j][e] = 0.f;

    ld_stage(gA, gB, lda, ldb, 0, sbase, tid);
    asm volatile("cp.async.commit_group;");
    for (int kt = 0; kt < nkt; kt++) {
        if (kt + 1 < nkt) {
            ld_stage(gA, gB, lda, ldb, kt + 1, sbase + ((kt + 1) & 1) * 32768, tid);
            asm volatile("cp.async.commit_group;");
            asm volatile("cp.async.wait_group 1;");
        } else {
            asm volatile("cp.async.wait_group 0;");
        }
        __syncthreads();
        uint32_t sAb = sbase + (kt & 1) * 32768;
        uint32_t sBb = sAb + 16384;
        #pragma unroll
        for (int ks = 0; ks < 2; ks++) {
            int kofH = (ks * 32 + hi16) ^ xr;
            int kofL = (64 + ks * 32 + hi16) ^ xr;
            uint32_t ah[4][4], al[4][4], bb[4][2];
            #pragma unroll
            for (int mi = 0; mi < 4; mi++) {
                uint32_t ad = sAb + aRowOff + mi * 2048;
                LDSM4(ah[mi][0], ah[mi][1], ah[mi][2], ah[mi][3], ad + kofH);
                if (NPROD == 3)
                    LDSM4(al[mi][0], al[mi][1], al[mi][2], al[mi][3], ad + kofL);
            }
            #pragma unroll
            for (int p = 0; p < 2; p++) {
                uint32_t t0, t1, t2, t3;
                LDSM4(t0, t1, t2, t3, sBb + bRowOff + p * 2048 + kofH);
                bb[p * 2][0] = t0; bb[p * 2][1] = t2;
                bb[p * 2 + 1][0] = t1; bb[p * 2 + 1][1] = t3;
            }
            #pragma unroll
            for (int mi = 0; mi < 4; mi++)
                #pragma unroll
                for (int ni = 0; ni < 4; ni++) {
                    MMA16816(acc[mi][ni], ah[mi], bb[ni]);
                    if (NPROD == 3) MMA16816(acc[mi][ni], al[mi], bb[ni]);
                }
            if (NPROD >= 2) {
                #pragma unroll
                for (int p = 0; p < 2; p++) {
                    uint32_t t0, t1, t2, t3;
                    LDSM4(t0, t1, t2, t3, sBb + bRowOff + p * 2048 + kofL);
                    bb[p * 2][0] = t0; bb[p * 2][1] = t2;
                    bb[p * 2 + 1][0] = t1; bb[p * 2 + 1][1] = t3;
                }
                #pragma unroll
                for (int mi = 0; mi < 4; mi++)
                    #pragma unroll
                    for (int ni = 0; ni < 4; ni++)
                        MMA16816(acc[mi][ni], ah[mi], bb[ni]);
            }
        }
        __syncthreads();
    }

    float alpha = alpha_ptr ? *alpha_ptr : 1.0f;
    float* Cb = C ? C + (size_t)b1 * sc1 + (size_t)b2 * sc2 : nullptr;
    bf* Csb = Cs ? Cs + (size_t)b1 * scs1 + (size_t)b2 * scs2 : nullptr;
    int rr = rowBase + wm + (lane >> 2);
    int cc0 = colBase + wn + (lane & 3) * 2;
    #pragma unroll
    for (int mi = 0; mi < 4; mi++) {
        #pragma unroll
        for (int ni = 0; ni < 4; ni++) {
            int gc = cc0 + ni * 8;
            #pragma unroll
            for (int half = 0; half < 2; half++) {
                int gr = rr + mi * 16 + half * 8;
                float2 v = make_float2(acc[mi][ni][half * 2], acc[mi][ni][half * 2 + 1]);
                v.x *= alpha; v.y *= alpha;
                if (bias) {
                    float2 bv = *(const float2*)&bias[gc];
                    v.x += bv.x; v.y += bv.y;
                }
                if (act) {
                    v.x = 0.5f * v.x * (1.0f + erff(v.x * 0.70710678118654752f));
                    v.y = 0.5f * v.y * (1.0f + erff(v.y * 0.70710678118654752f));
                }
                if (residual) {
                    float2 rv = *(const float2*)&residual[(size_t)gr * ldr + gc];
                    v.x += rv.x; v.y += rv.y;
                }
                if (Cb) *(float2*)&Cb[(size_t)gr * ldc + gc] = v;
                if (Csb) splitStore(Csb + (size_t)gr * ldcs + ((gc >> 5) * 64 + (gc & 31)), v.x, v.y);
            }
        }
    }
}

// ---------------- host helpers ----------------
static void gemmx(const bf* A, const bf* B, float* C, bf* Cs,
                  const float* bias, const float* res, const float* alpha,
                  int M, int N, int K, long lda, long ldb, long ldc, long ldr, long ldcs,
                  long sa1, long sa2, long sb1, long sb2, long sc1, long sc2, long scs1, long scs2,
                  int b1c, int b2c, int act, int nprod, int maskMode) {
    dim3 grid(M / 128, N / 128, b1c * b2c);
    if (nprod == 1) {
        cudaFuncSetAttribute(gemm_bf16_kernel<1>, cudaFuncAttributeMaxDynamicSharedMemorySize, 65536);
        gemm_bf16_kernel<1><<<grid, 256, 65536>>>(A, B, C, Cs, bias, res, alpha, K,
                                                  lda, ldb, ldc, ldr, ldcs,
                                                  sa1, sa2, sb1, sb2, sc1, sc2, scs1, scs2,
                                                  b2c, act, maskMode);
    } else {
        cudaFuncSetAttribute(gemm_bf16_kernel<3>, cudaFuncAttributeMaxDynamicSharedMemorySize, 65536);
        gemm_bf16_kernel<3><<<grid, 256, 65536>>>(A, B, C, Cs, bias, res, alpha, K,
                                                  lda, ldb, ldc, ldr, ldcs,
                                                  sa1, sa2, sb1, sb2, sc1, sc2, scs1, scs2,
                                                  b2c, act, maskMode);
    }
}
static void splitx(const float* src, int srcLd, long srcBS, bf* dst, int dstRowE,
                   long dstBSE, int dstRowOff, int R, int C, int nb) {
    dim3 grid((C + 1023) / 1024, R, nb);
    split_kernel<<<grid, 256>>>(src, srcLd, srcBS, dst, dstRowE, dstBSE, dstRowOff, C);
}
static void tsplitx(const float* src, int srcLd, long srcBS, bf* dst, int dstRowE,
                    long dstBSE, int R, int C, int nb) {
    dim3 grid(C / 32, R / 32, nb);
    tsplit_kernel<<<grid, dim3(32, 8)>>>(src, srcLd, srcBS, dst, dstRowE, dstBSE);
}
template <typename T>
static T* symp(const void* s) {
    void* p = nullptr;
    cudaGetSymbolAddress(&p, s);
    return (T*)p;
}

extern "C" void kernel_launch(void* const* d_in, const int* in_sizes, int n_in,
                              void* d_out, int out_size) {
    const int*   x         = (const int*)d_in[0];
    const float* mem       = (const float*)d_in[1];
    const float* lmem      = (const float*)d_in[2];
    const float* token_emb = (const float*)d_in[3];
    const float* pos_emb   = (const float*)d_in[4];
    const float* attn_ln_g = (const float*)d_in[5];
    const float* attn_ln_b = (const float*)d_in[6];
    const float* attn_wq   = (const float*)d_in[7];
    const float* attn_wkv  = (const float*)d_in[8];
    const float* attn_wo   = (const float*)d_in[9];
    const float* attn_bo   = (const float*)d_in[10];
    const float* ff_ln_g   = (const float*)d_in[11];
    const float* ff_ln_b   = (const float*)d_in[12];
    const float* ff_w1     = (const float*)d_in[13];
    const float* ff_b1     = (const float*)d_in[14];
    const float* ff_w2     = (const float*)d_in[15];
    const float* ff_b2     = (const float*)d_in[16];
    const float* logits_w  = (const float*)d_in[17];
    const float* logits_b  = (const float*)d_in[18];
    const float* mem_wq    = (const float*)d_in[19];
    const float* mem_wkv   = (const float*)d_in[20];
    const float* mem_wo    = (const float*)d_in[21];
    const float* rezero    = (const float*)d_in[22];

    float* out        = (float*)d_out;
    float* out_logits = out;
    float* out_mem    = out + (size_t)B_ * SEQ_ * VOCAB_;
    float* out_lmem   = out_mem + (size_t)DEPTH_ * B_ * SEQ_ * DIM_;

    float* h    = symp<float>(g_h);
    float* kv   = symp<float>(g_kv);
    float* qk   = symp<float>(g_qk);
    float* qp   = symp<float>(g_qp);
    float* kvm  = symp<float>(g_kvm);
    float* qm   = symp<float>(g_qm);
    float* ctx  = symp<float>(g_ctx);
    bf* wqT   = symp<bf>(s_wqT);
    bf* wkvT  = symp<bf>(s_wkvT);
    bf* woT   = symp<bf>(s_woT);
    bf* ffw1T = symp<bf>(s_ffw1T);
    bf* ffw2T = symp<bf>(s_ffw2T);
    bf* logwT = symp<bf>(s_logwT);
    bf* mwqT  = symp<bf>(s_mwqT);
    bf* mwkvT = symp<bf>(s_mwkvT);
    bf* mwoT  = symp<bf>(s_mwoT);
    bf* posS  = symp<bf>(s_posS);
    bf* kvinS = symp<bf>(s_kvinS);
    bf* qS    = symp<bf>(s_qS);
    bf* kvS   = symp<bf>(s_kvS);
    bf* vtS   = symp<bf>(s_vtS);
    bf* qkS   = symp<bf>(s_qkS);
    bf* aoS   = symp<bf>(s_aoS);
    bf* ainS  = symp<bf>(s_ainS);
    bf* ffS   = symp<bf>(s_ffS);
    bf* hS    = symp<bf>(s_hS);
    bf* kvinmS = symp<bf>(s_kvinmS);
    bf* ktS    = symp<bf>(s_ktS);
    bf* vtmS   = symp<bf>(s_vtmS);
    bf* qmS    = symp<bf>(s_qmS);
    bf* ctxTS  = symp<bf>(s_ctxTS);
    bf* outmS  = symp<bf>(s_outmS);

    const size_t rowBytes = sizeof(float) * DIM_;

    // ---- weight / pos transposes+splits ----
    tsplitx(attn_wq, DIM_, (long)DIM_ * DIM_, wqT, 2 * DIM_, (long)DIM_ * 2 * DIM_, DIM_, DIM_, DEPTH_);
    tsplitx(attn_wkv, 2 * DIM_, (long)DIM_ * 2 * DIM_, wkvT, 2 * DIM_, (long)2 * DIM_ * 2 * DIM_, DIM_, 2 * DIM_, DEPTH_);
    tsplitx(attn_wo, DIM_, (long)DIM_ * DIM_, woT, 2 * DIM_, (long)DIM_ * 2 * DIM_, DIM_, DIM_, DEPTH_);
    tsplitx(ff_w1, 4 * DIM_, (long)DIM_ * 4 * DIM_, ffw1T, 2 * DIM_, (long)4 * DIM_ * 2 * DIM_, DIM_, 4 * DIM_, DEPTH_);
    tsplitx(ff_w2, DIM_, (long)4 * DIM_ * DIM_, ffw2T, 8 * DIM_, (long)DIM_ * 8 * DIM_, 4 * DIM_, DIM_, DEPTH_);
    tsplitx(logits_w, VOCAB_, 0, logwT, 2 * DIM_, 0, DIM_, VOCAB_, 1);
    tsplitx(mem_wq, DIM_, 0, mwqT, 2 * DIM_, 0, DIM_, DIM_, 1);
    tsplitx(mem_wkv, 2 * DIM_, 0, mwkvT, 2 * DIM_, 0, DIM_, 2 * DIM_, 1);
    tsplitx(mem_wo, DIM_, 0, mwoT, 2 * DIM_, 0, DIM_, DIM_, 1);
    splitx(pos_emb, DH_, 0, posS, 2 * DH_, 0, 0, HEADS_ * KVLEN_, DH_, 1);

    gather_kernel<<<B_ * SEQ_, 256>>>(x, token_emb, h);

    for (int l = 0; l < DEPTH_; l++) {
        cudaMemcpyAsync(out_mem + (size_t)l * B_ * SEQ_ * DIM_, h,
                        (size_t)B_ * SEQ_ * rowBytes, cudaMemcpyDeviceToDevice, 0);
        layernorm_split_kernel<<<B_ * SEQ_, 256>>>(h, attn_ln_g + l * DIM_, attn_ln_b + l * DIM_,
                                                   kvinS, SEQ_, KVLEN_, LMEM_ + MEM_, 2 * DIM_);
        splitx(lmem + (size_t)l * B_ * LMEM_ * DIM_, DIM_, (long)LMEM_ * DIM_,
               kvinS, 2 * DIM_, (long)KVLEN_ * 2 * DIM_, 0, LMEM_, DIM_, B_);
        splitx(mem + (size_t)l * B_ * MEM_ * DIM_, DIM_, (long)MEM_ * DIM_,
               kvinS, 2 * DIM_, (long)KVLEN_ * 2 * DIM_, LMEM_, MEM_, DIM_, B_);
        // q = a_in @ wq -> qS
        gemmx(kvinS + (size_t)(LMEM_ + MEM_) * 2 * DIM_, wqT + (size_t)l * DIM_ * 2 * DIM_,
              nullptr, qS, nullptr, nullptr, nullptr,
              SEQ_, DIM_, DIM_, 2 * DIM_, 2 * DIM_, 0, 0, 2 * DIM_,
              (long)KVLEN_ * 2 * DIM_, 0, 0, 0, 0, 0, (long)SEQ_ * 2 * DIM_, 0, B_, 1, 0, 3, 0);
        // kv = kv_in @ wkv -> kv (fp32) + kvS
        gemmx(kvinS, wkvT + (size_t)l * 2 * DIM_ * 2 * DIM_, kv, kvS, nullptr, nullptr, nullptr,
              KVLEN_, 2 * DIM_, DIM_, 2 * DIM_, 2 * DIM_, 2 * DIM_, 0, 4 * DIM_,
              (long)KVLEN_ * 2 * DIM_, 0, 0, 0, (long)KVLEN_ * 2 * DIM_, 0,
              (long)KVLEN_ * 4 * DIM_, 0, B_, 1, 0, 3, 0);
        // vt = transpose(V half)
        tsplitx(kv + DIM_, 2 * DIM_, (long)KVLEN_ * 2 * DIM_, vtS, 2 * KVLEN_,
                (long)DIM_ * 2 * KVLEN_, KVLEN_, DIM_, B_);
        // QK^T (causal tile skip)
        gemmx(qS, kvS, qk, nullptr, nullptr, nullptr, nullptr,
              SEQ_, KVLEN_, DH_, 2 * DIM_, 4 * DIM_, KVLEN_, 0, 0,
              (long)SEQ_ * 2 * DIM_, 256, (long)KVLEN_ * 4 * DIM_, 256,
              (long)HEADS_ * SEQ_ * KVLEN_, (long)SEQ_ * KVLEN_, 0, 0, B_, HEADS_, 0, 3, 1);
        // Q PE^T (single product; shift-window tile skip)
        gemmx(qS, posS, qp, nullptr, nullptr, nullptr, nullptr,
              SEQ_, KVLEN_, DH_, 2 * DIM_, 2 * DH_, KVLEN_, 0, 0,
              (long)SEQ_ * 2 * DIM_, 256, 0, (long)KVLEN_ * 2 * DH_,
              (long)HEADS_ * SEQ_ * KVLEN_, (long)SEQ_ * KVLEN_, 0, 0, B_, HEADS_, 0, 1, 2);
        attn_softmax_kernel<<<B_ * HEADS_ * SEQ_, 256>>>(qk, qp, qkS);
        // attn @ V -> aoS (K capped per row tile)
        gemmx(qkS, vtS, nullptr, aoS, nullptr, nullptr, nullptr,
              SEQ_, DH_, KVLEN_, 2 * KVLEN_, 2 * KVLEN_, 0, 0, 2 * DIM_,
              (long)HEADS_ * SEQ_ * 2 * KVLEN_, (long)SEQ_ * 2 * KVLEN_,
              (long)DIM_ * 2 * KVLEN_, (long)DH_ * 2 * KVLEN_,
              0, 0, (long)SEQ_ * 2 * DIM_, 256, B_, HEADS_, 0, 3, 3);
        // h += ao @ wo + bo
        gemmx(aoS, woT + (size_t)l * DIM_ * 2 * DIM_, h, nullptr,
              attn_bo + l * DIM_, h, nullptr,
              B_ * SEQ_, DIM_, DIM_, 2 * DIM_, 2 * DIM_, DIM_, DIM_, 0,
              0, 0, 0, 0, 0, 0, 0, 0, 1, 1, 0, 3, 0);
        // FF
        layernorm_split_kernel<<<B_ * SEQ_, 256>>>(h, ff_ln_g + l * DIM_, ff_ln_b + l * DIM_,
                                                   ainS, B_ * SEQ_, 0, 0, 2 * DIM_);
        gemmx(ainS, ffw1T + (size_t)l * 4 * DIM_ * 2 * DIM_, nullptr, ffS,
              ff_b1 + (size_t)l * 4 * DIM_, nullptr, nullptr,
              B_ * SEQ_, 4 * DIM_, DIM_, 2 * DIM_, 2 * DIM_, 0, 0, 8 * DIM_,
              0, 0, 0, 0, 0, 0, 0, 0, 1, 1, 1, 3, 0);
        gemmx(ffS, ffw2T + (size_t)l * DIM_ * 8 * DIM_, h, hS,
              ff_b2 + l * DIM_, h, nullptr,
              B_ * SEQ_, DIM_, 4 * DIM_, 8 * DIM_, 8 * DIM_, DIM_, DIM_, 2 * DIM_,
              0, 0, 0, 0, 0, 0, 0, 0, 1, 1, 0, 3, 0);
    }

    // logits
    gemmx(hS, logwT, out_logits, nullptr, logits_b, nullptr, nullptr,
          B_ * SEQ_, VOCAB_, DIM_, 2 * DIM_, 2 * DIM_, VOCAB_, 0, 0,
          0, 0, 0, 0, 0, 0, 0, 0, 1, 1, 0, 3, 0);

    // ---------------- memory network ----------------
    layernorm_split_kernel<<<DEPTH_ * B_ * LMEM_, 256>>>(lmem, nullptr, nullptr,
                                                         kvinmS, LMEM_, KVLEN_, 0, 2 * DIM_);
    splitx(mem, DIM_, (long)MEM_ * DIM_, kvinmS, 2 * DIM_, (long)KVLEN_ * 2 * DIM_,
           LMEM_, MEM_, DIM_, DEPTH_ * B_);
    splitx(out_mem, DIM_, (long)SEQ_ * DIM_, kvinmS, 2 * DIM_, (long)KVLEN_ * 2 * DIM_,
           LMEM_ + MEM_, SEQ_, DIM_, DEPTH_ * B_);
    // qm = nl @ wq
    gemmx(kvinmS, mwqT, qm, nullptr, nullptr, nullptr, nullptr,
          LMEM_, DIM_, DIM_, 2 * DIM_, 2 * DIM_, DIM_, 0, 0,
          (long)KVLEN_ * 2 * DIM_, 0, 0, 0, (long)LMEM_ * DIM_, 0, 0, 0, DEPTH_ * B_, 1, 0, 3, 0);
    head_softmax_kernel<<<DEPTH_ * B_ * LMEM_ * HEADS_, 128>>>(qm);
    splitx(qm, DIM_, (long)LMEM_ * DIM_, qmS, 2 * DIM_, (long)LMEM_ * 2 * DIM_,
           0, LMEM_, DIM_, DEPTH_ * B_);
    // kvm = kvinm @ wkv
    gemmx(kvinmS, mwkvT, kvm, nullptr, nullptr, nullptr, nullptr,
          KVLEN_, 2 * DIM_, DIM_, 2 * DIM_, 2 * DIM_, 2 * DIM_, 0, 0,
          (long)KVLEN_ * 2 * DIM_, 0, 0, 0, (long)KVLEN_ * 2 * DIM_, 0, 0, 0, DEPTH_ * B_, 1, 0, 3, 0);
    col_softmax_kernel<<<dim3(32, DEPTH_ * B_), dim3(32, 8)>>>(kvm);
    tsplitx(kvm, 2 * DIM_, (long)KVLEN_ * 2 * DIM_, ktS, 2 * KVLEN_,
            (long)DIM_ * 2 * KVLEN_, KVLEN_, DIM_, DEPTH_ * B_);
    tsplitx(kvm + DIM_, 2 * DIM_, (long)KVLEN_ * 2 * DIM_, vtmS, 2 * KVLEN_,
            (long)DIM_ * 2 * KVLEN_, KVLEN_, DIM_, DEPTH_ * B_);
    // ctx = k^T v
    gemmx(ktS, vtmS, ctx, nullptr, nullptr, nullptr, nullptr,
          DH_, DH_, KVLEN_, 2 * KVLEN_, 2 * KVLEN_, DH_, 0, 0,
          (long)DIM_ * 2 * KVLEN_, (long)DH_ * 2 * KVLEN_,
          (long)DIM_ * 2 * KVLEN_, (long)DH_ * 2 * KVLEN_,
          (long)HEADS_ * DH_ * DH_, (long)DH_ * DH_, 0, 0, DEPTH_ * B_, HEADS_, 0, 3, 0);
    tsplitx(ctx, DH_, (long)DH_ * DH_, ctxTS, 2 * DH_, (long)DH_ * 2 * DH_,
            DH_, DH_, DEPTH_ * B_ * HEADS_);
    // outm = q @ ctx -> outmS
    gemmx(qmS, ctxTS, nullptr, outmS, nullptr, nullptr, nullptr,
          LMEM_, DH_, DH_, 2 * DIM_, 2 * DH_, 0, 0, 2 * DIM_,
          (long)LMEM_ * 2 * DIM_, 256, (long)HEADS_ * DH_ * 2 * DH_, (long)DH_ * 2 * DH_,
          0, 0, (long)LMEM_ * 2 * DIM_, 256, DEPTH_ * B_, HEADS_, 0, 3, 0);
    // next_lmem = rezero*(outm @ wo) + lmem
    gemmx(outmS, mwoT, out_lmem, nullptr, nullptr, lmem, rezero,
          DEPTH_ * B_ * LMEM_, DIM_, DIM_, 2 * DIM_, 2 * DIM_, DIM_, DIM_, 0,
          0, 0, 0, 0, 0, 0, 0, 0, 1, 1, 0, 3, 0);
}